// round 6
// baseline (speedup 1.0000x reference)
#include <cuda_runtime.h>
#include <math.h>

#define BB 8
#define T_OUT 256
#define T_IN 512
#define LL 128
#define D_IN 128
#define D_ATT 128

#define KR 10          // register-resident k-values per thread (40 weight regs)
#define KSH 6          // shared-resident k-values per thread (96 KB smem)

// scratch (no allocs allowed)
__device__ float g_xz[BB * T_OUT * 4 * LL];    // input projection, GATE-QUAD layout:
                                               // g_xz[(b,t)*128 + j] = float4(zi,zf,zg,zo)
__device__ float g_keys[BB * T_IN * LL];       // attended @ W1 + b1

#define FMA2(acc, a, b) asm("fma.rn.f32x2 %0, %1, %2, %0;" : "+l"(acc) : "l"(a), "l"(b))
#define ADD2(acc, a)    asm("add.rn.f32x2 %0, %1, %0;"     : "+l"(acc) : "l"(a))

#define BAR_SYNC(id)   asm volatile("bar.sync %0, 1024;"   :: "r"(id) : "memory")
#define BAR_ARRIVE(id) asm volatile("bar.arrive %0, 1024;" :: "r"(id) : "memory")

__device__ __forceinline__ unsigned long long pack2(float a, float b) {
    float2 t = make_float2(a, b);
    return *reinterpret_cast<unsigned long long*>(&t);
}
__device__ __forceinline__ float lo2(unsigned long long v) {
    return reinterpret_cast<float2*>(&v)->x;
}
__device__ __forceinline__ float hi2(unsigned long long v) {
    return reinterpret_cast<float2*>(&v)->y;
}

// fast gates via ex2-based __expf (validated: R2 rel_err 4.8e-7)
__device__ __forceinline__ float sig_f(float x) {
    return __fdividef(1.0f, 1.0f + __expf(-x));
}
__device__ __forceinline__ float tanh_f(float x) {
    return 1.0f - __fdividef(2.0f, 1.0f + __expf(2.0f * x));
}

// ---------------------------------------------------------------------------
// K1: xz (gate-quad layout).  grid = B*T_OUT/8 = 256, blk 128; 8 rows per CTA
// ---------------------------------------------------------------------------
__global__ void __launch_bounds__(128) k_xz(const float* __restrict__ inp,
                                            const float* __restrict__ Wk,
                                            const float* __restrict__ bias) {
    int row0 = blockIdx.x * 8;
    int j = threadIdx.x;
    __shared__ float in_sh[8][128];
    for (int i = j; i < 8 * 128; i += 128)
        in_sh[i >> 7][i & 127] = inp[row0 * D_IN + i];
    __syncthreads();

    float bx = bias[j], by = bias[j + 128], bz = bias[j + 256], bw = bias[j + 384];
    float4 acc[8];
#pragma unroll
    for (int r = 0; r < 8; r++) acc[r] = make_float4(bx, by, bz, bw);

#pragma unroll 2
    for (int k = 0; k < 128; k++) {
        float wi = Wk[k * 512 + j];
        float wf = Wk[k * 512 + 128 + j];
        float wg = Wk[k * 512 + 256 + j];
        float wo = Wk[k * 512 + 384 + j];
#pragma unroll
        for (int r = 0; r < 8; r++) {
            float x = in_sh[r][k];
            acc[r].x = fmaf(x, wi, acc[r].x);
            acc[r].y = fmaf(x, wf, acc[r].y);
            acc[r].z = fmaf(x, wg, acc[r].z);
            acc[r].w = fmaf(x, wo, acc[r].w);
        }
    }
#pragma unroll
    for (int r = 0; r < 8; r++)
        ((float4*)g_xz)[(size_t)(row0 + r) * 128 + j] = acc[r];
}

// ---------------------------------------------------------------------------
// K2: keys = attended @ W1 + b1.  grid = B*T_IN/8 = 512, blk 128; 8 rows/CTA
// ---------------------------------------------------------------------------
__global__ void __launch_bounds__(128) k_keys(const float* __restrict__ att,
                                              const float* __restrict__ W1,
                                              const float* __restrict__ b1) {
    int row0 = blockIdx.x * 8;
    int j = threadIdx.x;
    __shared__ float a_sh[8][128];
    for (int i = j; i < 8 * 128; i += 128)
        a_sh[i >> 7][i & 127] = att[row0 * D_ATT + i];
    __syncthreads();

    float acc[8];
    float bj = b1[j];
#pragma unroll
    for (int r = 0; r < 8; r++) acc[r] = bj;

#pragma unroll 4
    for (int k = 0; k < 128; k++) {
        float w = W1[k * LL + j];
#pragma unroll
        for (int r = 0; r < 8; r++) acc[r] = fmaf(a_sh[r][k], w, acc[r]);
    }
#pragma unroll
    for (int r = 0; r < 8; r++)
        g_keys[(size_t)(row0 + r) * LL + j] = acc[r];
}

// ---------------------------------------------------------------------------
// K3: LSTM, register+shared resident weights.  grid = B, blk 1024.
// tid = ks*128 + j: thread owns gate-quad cols {j, j+128, j+256, j+384},
// k-slice [16ks, 16ks+16). First KR k in registers, last KSH k in shared.
// Named-barrier split: bar 1 = partials ready, bar 2 = h ready.
// dyn smem: sW (96KB) | pbuf (16KB, ulonglong2) | h2 (1KB)
// ---------------------------------------------------------------------------
__global__ void __launch_bounds__(1024, 1) k_lstm(const float* __restrict__ Wr,
                                                  float* __restrict__ out) {
    extern __shared__ unsigned char dynsmem[];
    float4* sW = (float4*)dynsmem;                                   // 6144 float4
    ulonglong2* pbuf = (ulonglong2*)(dynsmem + 98304);               // 1024 x 16B
    unsigned long long* h2 = (unsigned long long*)(dynsmem + 98304 + 16384);  // 128

    int b = blockIdx.x;
    int tid = threadIdx.x;
    int j = tid & 127;
    int ks = tid >> 7;
    int k0 = ks << 4;

    // register weights: quad (i,f,g,o) packed as two f32x2
    unsigned long long wA[KR], wB[KR];
#pragma unroll
    for (int r = 0; r < KR; r++) {
        const float* row = Wr + (size_t)(k0 + r) * 512;
        wA[r] = pack2(row[j], row[128 + j]);
        wB[r] = pack2(row[256 + j], row[384 + j]);
    }
    // shared weights (pre-quadded)
#pragma unroll
    for (int kk = 0; kk < KSH; kk++) {
        const float* row = Wr + (size_t)(k0 + KR + kk) * 512;
        sW[(ks * KSH + kk) * 128 + j] =
            make_float4(row[j], row[128 + j], row[256 + j], row[384 + j]);
    }
    if (tid < 128) h2[tid] = 0ull;
    float c = 0.0f;

    const ulonglong2* xz2 = (const ulonglong2*)g_xz + (size_t)b * T_OUT * 128;
    const float4* sWrow = sW + (ks * KSH) * 128 + j;
    const unsigned long long* hA = h2 + k0;
    __syncthreads();

    for (int t = 0; t < T_OUT; t++) {
        // prefetch xz for this step (h-independent; hides L2 latency under FMA)
        unsigned long long z01 = 0ull, z23 = 0ull;
        if (tid < 128) {
            ulonglong2 xv = xz2[t * 128 + tid];
            z01 = xv.x;                      // (zi, zf)
            z23 = xv.y;                      // (zg, zo)
        }

        unsigned long long a01 = 0ull, a23 = 0ull;
#pragma unroll
        for (int r = 0; r < KR; r++) {
            unsigned long long hh = hA[r];
            FMA2(a01, hh, wA[r]);
            FMA2(a23, hh, wB[r]);
        }
#pragma unroll
        for (int kk = 0; kk < KSH; kk++) {
            unsigned long long hh = hA[KR + kk];
            float4 w = sWrow[kk * 128];
            unsigned long long wa = pack2(w.x, w.y);
            unsigned long long wb = pack2(w.z, w.w);
            FMA2(a01, hh, wa);
            FMA2(a23, hh, wb);
        }
        pbuf[tid] = make_ulonglong2(a01, a23);

        if (tid >= 128) {
            BAR_ARRIVE(1);                   // partials published
            BAR_SYNC(2);                     // sleep until h ready
        } else {
            BAR_SYNC(1);                     // wait for all partials
#pragma unroll
            for (int s = 0; s < 8; s++) {
                ulonglong2 p = pbuf[s * 128 + tid];
                ADD2(z01, p.x);
                ADD2(z23, p.y);
            }
            float zi = lo2(z01), zf = hi2(z01), zg = lo2(z23), zo = hi2(z23);
            c = sig_f(zf) * c + sig_f(zi) * tanh_f(zg);
            float h = sig_f(zo) * tanh_f(c);
            h2[tid] = pack2(h, h);
            out[(size_t)(b * T_OUT + t) * 256 + tid] = h;
            BAR_SYNC(2);                     // publish h, release sleepers
        }
    }

    if (tid < 128) {
        size_t base = (size_t)BB * T_OUT * 256;
        out[base + b * LL + tid] = lo2(h2[tid]);               // h_T
        out[base + BB * LL + b * LL + tid] = c;                // c_T
    }
}

// ---------------------------------------------------------------------------
// K4: attention.  grid = B*(T_OUT/4) = 512 CTAs, blk 512 (16 warps), 4 q rows.
// ---------------------------------------------------------------------------
__global__ void __launch_bounds__(512) k_attn(const float* __restrict__ attended,
                                              const float* __restrict__ W2,
                                              const float* __restrict__ b2,
                                              const float* __restrict__ W3,
                                              const float* __restrict__ b3,
                                              float* __restrict__ out) {
    int b  = blockIdx.x >> 6;
    int t0 = (blockIdx.x & 63) * 4;
    int tid = threadIdx.x;
    int lane = tid & 31;
    int w = tid >> 5;                 // 0..15

    __shared__ float xs[4][128];
    __shared__ float q_sh[4][132];
    __shared__ float sc[4][520];
    __shared__ float inv_sh[4];
    __shared__ float4 rbuf[16][32];

    // stage x rows (512 floats, one per thread)
    {
        int r = tid >> 7, col = tid & 127;
        xs[r][col] = out[(size_t)(b * T_OUT + t0 + r) * 256 + col];
    }
    __syncthreads();

    // phase 0: q rows — warps 0..3 compute row w
    if (w < 4) {
        const float4* W24 = (const float4*)W2;   // (128, 32 float4)
        float4 acc = ((const float4*)b2)[lane];
#pragma unroll 8
        for (int m = 0; m < 128; m++) {
            float x = xs[w][m];
            float4 ww = W24[m * 32 + lane];
            acc.x = fmaf(x, ww.x, acc.x);
            acc.y = fmaf(x, ww.y, acc.y);
            acc.z = fmaf(x, ww.z, acc.z);
            acc.w = fmaf(x, ww.w, acc.w);
        }
        *(float4*)&q_sh[w][4 * lane] = acc;
    }
    __syncthreads();

    // register preload
    float w3r[4], qv[4][4];
#pragma unroll
    for (int cc = 0; cc < 4; cc++) {
        w3r[cc] = W3[lane + 32 * cc];
#pragma unroll
        for (int q = 0; q < 4; q++) qv[q][cc] = q_sh[q][lane + 32 * cc];
    }
    float b3v = b3[0];

    // phase 1: scores (MUFU-bound)
    const float* keyb = g_keys + (size_t)b * T_IN * LL;
    for (int k = w; k < T_IN; k += 16) {
        const float* kr = keyb + k * LL;
        float kv[4];
#pragma unroll
        for (int cc = 0; cc < 4; cc++) kv[cc] = kr[lane + 32 * cc];
#pragma unroll
        for (int q = 0; q < 4; q++) {
            float p = 0.0f;
#pragma unroll
            for (int cc = 0; cc < 4; cc++) {
                float x = kv[cc] + qv[q][cc];
                float th;
                asm("tanh.approx.f32 %0, %1;" : "=f"(th) : "f"(x));
                p = fmaf(th, w3r[cc], p);
            }
#pragma unroll
            for (int o = 16; o; o >>= 1) p += __shfl_xor_sync(0xffffffffu, p, o);
            if (lane == q) sc[q][k] = p + b3v;
        }
    }
    __syncthreads();

    // phase 2: softmax — warps 0..3
    if (w < 4) {
        float m = -1e30f;
        for (int jj = lane; jj < T_IN; jj += 32) m = fmaxf(m, sc[w][jj]);
#pragma unroll
        for (int o = 16; o; o >>= 1) m = fmaxf(m, __shfl_xor_sync(0xffffffffu, m, o));
        float s = 0.0f;
        for (int jj = lane; jj < T_IN; jj += 32) {
            float e = __expf(sc[w][jj] - m);
            sc[w][jj] = e;
            s += e;
        }
#pragma unroll
        for (int o = 16; o; o >>= 1) s += __shfl_xor_sync(0xffffffffu, s, o);
        if (lane == 0) inv_sh[w] = 1.0f / s;
    }
    __syncthreads();

    // phase 3: weighted sum
    float4 acc[4];
#pragma unroll
    for (int q = 0; q < 4; q++) acc[q] = make_float4(0.f, 0.f, 0.f, 0.f);
    const float4* att4 = (const float4*)(attended + (size_t)b * T_IN * D_ATT);
    for (int k = w; k < T_IN; k += 16) {
        float4 a = att4[k * 32 + lane];
#pragma unroll
        for (int q = 0; q < 4; q++) {
            float s = sc[q][k];
            acc[q].x = fmaf(s, a.x, acc[q].x);
            acc[q].y = fmaf(s, a.y, acc[q].y);
            acc[q].z = fmaf(s, a.z, acc[q].z);
            acc[q].w = fmaf(s, a.w, acc[q].w);
        }
    }
#pragma unroll 1
    for (int q = 0; q < 4; q++) {
        __syncthreads();
        rbuf[w][lane] = acc[q];
        __syncthreads();
        if (w == q) {                     // warp q finalizes row q
            float4 s = rbuf[0][lane];
#pragma unroll
            for (int ww = 1; ww < 16; ww++) {
                float4 u = rbuf[ww][lane];
                s.x += u.x; s.y += u.y; s.z += u.z; s.w += u.w;
            }
            float inv = inv_sh[q];
            s.x *= inv; s.y *= inv; s.z *= inv; s.w *= inv;
            ((float4*)out)[(size_t)(b * T_OUT + t0 + q) * 64 + 32 + lane] = s;
        }
    }
}

// ---------------------------------------------------------------------------
extern "C" void kernel_launch(void* const* d_in, const int* in_sizes, int n_in,
                              void* d_out, int out_size) {
    const float* inputs   = (const float*)d_in[0];
    const float* attended = (const float*)d_in[1];
    const float* Wk       = (const float*)d_in[2];
    const float* Wr       = (const float*)d_in[3];
    const float* bias     = (const float*)d_in[4];
    const float* W1       = (const float*)d_in[5];
    const float* b1       = (const float*)d_in[6];
    const float* W2       = (const float*)d_in[7];
    const float* b2       = (const float*)d_in[8];
    const float* W3       = (const float*)d_in[9];
    const float* b3       = (const float*)d_in[10];
    float* out = (float*)d_out;

    const int lstm_smem = 98304 + 16384 + 1024;   // 115712 B
    cudaFuncSetAttribute(k_lstm, cudaFuncAttributeMaxDynamicSharedMemorySize, lstm_smem);

    k_xz<<<BB * T_OUT / 8, 128>>>(inputs, Wk, bias);
    k_keys<<<BB * T_IN / 8, 128>>>(attended, W1, b1);
    k_lstm<<<BB, 1024, lstm_smem>>>(Wr, out);
    k_attn<<<BB * (T_OUT / 4), 512>>>(attended, W2, b2, W3, b3, out);
}

// round 7
// speedup vs baseline: 1.2875x; 1.2875x over previous
#include <cuda_runtime.h>
#include <math.h>

#define BB 8
#define T_OUT 256
#define T_IN 512
#define LL 128
#define D_IN 128
#define D_ATT 128

#define KR 24          // register-resident k-values per thread (96 weight regs)
#define KSH 8          // shared-resident k-values per thread (64 KB smem)

// scratch (no allocs allowed)
__device__ float g_xz[BB * T_OUT * 4 * LL];    // input projection, GATE-QUAD layout:
                                               // g_xz[(b,t)*128 + j] = float4(zi,zf,zg,zo)
__device__ float g_keys[BB * T_IN * LL];       // attended @ W1 + b1

#define FMA2(acc, a, b) asm("fma.rn.f32x2 %0, %1, %2, %0;" : "+l"(acc) : "l"(a), "l"(b))
#define ADD2(acc, a)    asm("add.rn.f32x2 %0, %1, %0;"     : "+l"(acc) : "l"(a))

#define BAR_SYNC(id)   asm volatile("bar.sync %0, 512;"   :: "r"(id) : "memory")
#define BAR_ARRIVE(id) asm volatile("bar.arrive %0, 512;" :: "r"(id) : "memory")

__device__ __forceinline__ unsigned long long pack2(float a, float b) {
    float2 t = make_float2(a, b);
    return *reinterpret_cast<unsigned long long*>(&t);
}
__device__ __forceinline__ float lo2(unsigned long long v) {
    return reinterpret_cast<float2*>(&v)->x;
}
__device__ __forceinline__ float hi2(unsigned long long v) {
    return reinterpret_cast<float2*>(&v)->y;
}

// fast gates via ex2-based __expf (validated across rounds: rel_err ~5e-7)
__device__ __forceinline__ float sig_f(float x) {
    return __fdividef(1.0f, 1.0f + __expf(-x));
}
__device__ __forceinline__ float tanh_f(float x) {
    return 1.0f - __fdividef(2.0f, 1.0f + __expf(2.0f * x));
}

// ---------------------------------------------------------------------------
// K1: xz (gate-quad layout).  grid = B*T_OUT/8 = 256, blk 128; 8 rows per CTA
// ---------------------------------------------------------------------------
__global__ void __launch_bounds__(128) k_xz(const float* __restrict__ inp,
                                            const float* __restrict__ Wk,
                                            const float* __restrict__ bias) {
    int row0 = blockIdx.x * 8;
    int j = threadIdx.x;
    __shared__ float in_sh[8][128];
    for (int i = j; i < 8 * 128; i += 128)
        in_sh[i >> 7][i & 127] = inp[row0 * D_IN + i];
    __syncthreads();

    float bx = bias[j], by = bias[j + 128], bz = bias[j + 256], bw = bias[j + 384];
    float4 acc[8];
#pragma unroll
    for (int r = 0; r < 8; r++) acc[r] = make_float4(bx, by, bz, bw);

#pragma unroll 2
    for (int k = 0; k < 128; k++) {
        float wi = Wk[k * 512 + j];
        float wf = Wk[k * 512 + 128 + j];
        float wg = Wk[k * 512 + 256 + j];
        float wo = Wk[k * 512 + 384 + j];
#pragma unroll
        for (int r = 0; r < 8; r++) {
            float x = in_sh[r][k];
            acc[r].x = fmaf(x, wi, acc[r].x);
            acc[r].y = fmaf(x, wf, acc[r].y);
            acc[r].z = fmaf(x, wg, acc[r].z);
            acc[r].w = fmaf(x, wo, acc[r].w);
        }
    }
#pragma unroll
    for (int r = 0; r < 8; r++)
        ((float4*)g_xz)[(size_t)(row0 + r) * 128 + j] = acc[r];
}

// ---------------------------------------------------------------------------
// K2: keys = attended @ W1 + b1.  grid = B*T_IN/8 = 512, blk 128; 8 rows/CTA
// ---------------------------------------------------------------------------
__global__ void __launch_bounds__(128) k_keys(const float* __restrict__ att,
                                              const float* __restrict__ W1,
                                              const float* __restrict__ b1) {
    int row0 = blockIdx.x * 8;
    int j = threadIdx.x;
    __shared__ float a_sh[8][128];
    for (int i = j; i < 8 * 128; i += 128)
        a_sh[i >> 7][i & 127] = att[row0 * D_ATT + i];
    __syncthreads();

    float acc[8];
    float bj = b1[j];
#pragma unroll
    for (int r = 0; r < 8; r++) acc[r] = bj;

#pragma unroll 4
    for (int k = 0; k < 128; k++) {
        float w = W1[k * LL + j];
#pragma unroll
        for (int r = 0; r < 8; r++) acc[r] = fmaf(a_sh[r][k], w, acc[r]);
    }
#pragma unroll
    for (int r = 0; r < 8; r++)
        g_keys[(size_t)(row0 + r) * LL + j] = acc[r];
}

// ---------------------------------------------------------------------------
// K3: LSTM.  grid = B, blk 512 (128-reg budget per thread).
// tid = ks*128 + j: thread owns gate-quad cols {j, j+128, j+256, j+384},
// k-slice [32ks, 32ks+32). First KR=24 k in registers, last KSH=8 in shared.
// Crossbar/step = 64KB/128B = 512 cyc = FFMA2 issue floor (balanced).
// Named-barrier split: bar 1 = partials ready, bar 2 = h ready.
// dyn smem: sW (64KB) | pbuf (8KB, ulonglong2) | h2 (1KB)
// ---------------------------------------------------------------------------
__global__ void __launch_bounds__(512, 1) k_lstm(const float* __restrict__ Wr,
                                                 float* __restrict__ out) {
    extern __shared__ unsigned char dynsmem[];
    float4* sW = (float4*)dynsmem;                                        // 4096 float4
    ulonglong2* pbuf = (ulonglong2*)(dynsmem + 65536);                    // 512 x 16B
    unsigned long long* h2 = (unsigned long long*)(dynsmem + 65536 + 8192);  // 128

    int b = blockIdx.x;
    int tid = threadIdx.x;
    int j = tid & 127;
    int ks = tid >> 7;          // 0..3
    int k0 = ks << 5;           // 32 k per slice

    // register weights: quad (i,f,g,o) packed as two f32x2
    unsigned long long wA[KR], wB[KR];
#pragma unroll
    for (int r = 0; r < KR; r++) {
        const float* row = Wr + (size_t)(k0 + r) * 512;
        wA[r] = pack2(row[j], row[128 + j]);
        wB[r] = pack2(row[256 + j], row[384 + j]);
    }
    // shared weights (pre-quadded)
#pragma unroll
    for (int kk = 0; kk < KSH; kk++) {
        const float* row = Wr + (size_t)(k0 + KR + kk) * 512;
        sW[(ks * KSH + kk) * 128 + j] =
            make_float4(row[j], row[128 + j], row[256 + j], row[384 + j]);
    }
    if (tid < 128) h2[tid] = 0ull;
    float c = 0.0f;

    const ulonglong2* xz2 = (const ulonglong2*)g_xz + (size_t)b * T_OUT * 128;
    const float4* sWrow = sW + (ks * KSH) * 128 + j;
    const unsigned long long* hA = h2 + k0;
    __syncthreads();

    for (int t = 0; t < T_OUT; t++) {
        // prefetch xz for this step (h-independent; hides under FMA phase)
        unsigned long long z01 = 0ull, z23 = 0ull;
        if (tid < 128) {
            ulonglong2 xv = xz2[t * 128 + tid];
            z01 = xv.x;                      // (zi, zf)
            z23 = xv.y;                      // (zg, zo)
        }

        unsigned long long a01 = 0ull, a23 = 0ull;
#pragma unroll
        for (int r = 0; r < KR; r++) {
            unsigned long long hh = hA[r];
            FMA2(a01, hh, wA[r]);
            FMA2(a23, hh, wB[r]);
        }
#pragma unroll
        for (int kk = 0; kk < KSH; kk++) {
            unsigned long long hh = hA[KR + kk];
            float4 w = sWrow[kk * 128];
            unsigned long long wa = pack2(w.x, w.y);
            unsigned long long wb = pack2(w.z, w.w);
            FMA2(a01, hh, wa);
            FMA2(a23, hh, wb);
        }
        pbuf[tid] = make_ulonglong2(a01, a23);

        if (tid >= 128) {
            BAR_ARRIVE(1);                   // partials published
            BAR_SYNC(2);                     // sleep until h ready
        } else {
            BAR_SYNC(1);                     // wait for all partials
#pragma unroll
            for (int s = 0; s < 4; s++) {
                ulonglong2 p = pbuf[s * 128 + tid];
                ADD2(z01, p.x);
                ADD2(z23, p.y);
            }
            float zi = lo2(z01), zf = hi2(z01), zg = lo2(z23), zo = hi2(z23);
            c = sig_f(zf) * c + sig_f(zi) * tanh_f(zg);
            float h = sig_f(zo) * tanh_f(c);
            h2[tid] = pack2(h, h);
            out[(size_t)(b * T_OUT + t) * 256 + tid] = h;
            BAR_SYNC(2);                     // publish h, release sleepers
        }
    }

    if (tid < 128) {
        size_t base = (size_t)BB * T_OUT * 256;
        out[base + b * LL + tid] = lo2(h2[tid]);               // h_T
        out[base + BB * LL + b * LL + tid] = c;                // c_T
    }
}

// ---------------------------------------------------------------------------
// K4: attention.  grid = B*(T_OUT/2) = 1024 CTAs, blk 256 (8 warps), 2 q rows.
// Same per-warp structure as the 94us R2 version, double the grid parallelism.
// ---------------------------------------------------------------------------
__global__ void __launch_bounds__(256) k_attn(const float* __restrict__ attended,
                                              const float* __restrict__ W2,
                                              const float* __restrict__ b2,
                                              const float* __restrict__ W3,
                                              const float* __restrict__ b3,
                                              float* __restrict__ out) {
    int b  = blockIdx.x >> 7;                 // 128 CTAs per batch
    int t0 = (blockIdx.x & 127) * 2;
    int tid = threadIdx.x;
    int lane = tid & 31;
    int w = tid >> 5;                         // 0..7

    __shared__ float xs[2][128];
    __shared__ float q_sh[2][132];
    __shared__ float sc[2][520];
    __shared__ float inv_sh[2];
    __shared__ float4 rbuf[8][32];

    // stage x rows (256 floats, one per thread)
    {
        int r = tid >> 7, col = tid & 127;
        xs[r][col] = out[(size_t)(b * T_OUT + t0 + r) * 256 + col];
    }
    __syncthreads();

    // phase 0: q rows — warps 0,1 compute rows 0,1
    if (w < 2) {
        const float4* W24 = (const float4*)W2;   // (128, 32 float4)
        float4 acc = ((const float4*)b2)[lane];
#pragma unroll 8
        for (int m = 0; m < 128; m++) {
            float x = xs[w][m];
            float4 ww = W24[m * 32 + lane];
            acc.x = fmaf(x, ww.x, acc.x);
            acc.y = fmaf(x, ww.y, acc.y);
            acc.z = fmaf(x, ww.z, acc.z);
            acc.w = fmaf(x, ww.w, acc.w);
        }
        *(float4*)&q_sh[w][4 * lane] = acc;
    }
    __syncthreads();

    // register preload
    float w3r[4], qv[2][4];
#pragma unroll
    for (int cc = 0; cc < 4; cc++) {
        w3r[cc] = W3[lane + 32 * cc];
#pragma unroll
        for (int q = 0; q < 2; q++) qv[q][cc] = q_sh[q][lane + 32 * cc];
    }
    float b3v = b3[0];

    // phase 1: scores (MUFU-bound)
    const float* keyb = g_keys + (size_t)b * T_IN * LL;
    for (int k = w; k < T_IN; k += 8) {
        const float* kr = keyb + k * LL;
        float kv[4];
#pragma unroll
        for (int cc = 0; cc < 4; cc++) kv[cc] = kr[lane + 32 * cc];
#pragma unroll
        for (int q = 0; q < 2; q++) {
            float p = 0.0f;
#pragma unroll
            for (int cc = 0; cc < 4; cc++) {
                float x = kv[cc] + qv[q][cc];
                float th;
                asm("tanh.approx.f32 %0, %1;" : "=f"(th) : "f"(x));
                p = fmaf(th, w3r[cc], p);
            }
#pragma unroll
            for (int o = 16; o; o >>= 1) p += __shfl_xor_sync(0xffffffffu, p, o);
            if (lane == q) sc[q][k] = p + b3v;
        }
    }
    __syncthreads();

    // phase 2: softmax — warps 0,1
    if (w < 2) {
        float m = -1e30f;
        for (int jj = lane; jj < T_IN; jj += 32) m = fmaxf(m, sc[w][jj]);
#pragma unroll
        for (int o = 16; o; o >>= 1) m = fmaxf(m, __shfl_xor_sync(0xffffffffu, m, o));
        float s = 0.0f;
        for (int jj = lane; jj < T_IN; jj += 32) {
            float e = __expf(sc[w][jj] - m);
            sc[w][jj] = e;
            s += e;
        }
#pragma unroll
        for (int o = 16; o; o >>= 1) s += __shfl_xor_sync(0xffffffffu, s, o);
        if (lane == 0) inv_sh[w] = 1.0f / s;
    }
    __syncthreads();

    // phase 3: weighted sum
    float4 acc[2];
#pragma unroll
    for (int q = 0; q < 2; q++) acc[q] = make_float4(0.f, 0.f, 0.f, 0.f);
    const float4* att4 = (const float4*)(attended + (size_t)b * T_IN * D_ATT);
    for (int k = w; k < T_IN; k += 8) {
        float4 a = att4[k * 32 + lane];
#pragma unroll
        for (int q = 0; q < 2; q++) {
            float s = sc[q][k];
            acc[q].x = fmaf(s, a.x, acc[q].x);
            acc[q].y = fmaf(s, a.y, acc[q].y);
            acc[q].z = fmaf(s, a.z, acc[q].z);
            acc[q].w = fmaf(s, a.w, acc[q].w);
        }
    }
#pragma unroll 1
    for (int q = 0; q < 2; q++) {
        __syncthreads();
        rbuf[w][lane] = acc[q];
        __syncthreads();
        if (w == q) {                     // warp q finalizes row q
            float4 s = rbuf[0][lane];
#pragma unroll
            for (int ww = 1; ww < 8; ww++) {
                float4 u = rbuf[ww][lane];
                s.x += u.x; s.y += u.y; s.z += u.z; s.w += u.w;
            }
            float inv = inv_sh[q];
            s.x *= inv; s.y *= inv; s.z *= inv; s.w *= inv;
            ((float4*)out)[(size_t)(b * T_OUT + t0 + q) * 64 + 32 + lane] = s;
        }
    }
}

// ---------------------------------------------------------------------------
extern "C" void kernel_launch(void* const* d_in, const int* in_sizes, int n_in,
                              void* d_out, int out_size) {
    const float* inputs   = (const float*)d_in[0];
    const float* attended = (const float*)d_in[1];
    const float* Wk       = (const float*)d_in[2];
    const float* Wr       = (const float*)d_in[3];
    const float* bias     = (const float*)d_in[4];
    const float* W1       = (const float*)d_in[5];
    const float* b1       = (const float*)d_in[6];
    const float* W2       = (const float*)d_in[7];
    const float* b2       = (const float*)d_in[8];
    const float* W3       = (const float*)d_in[9];
    const float* b3       = (const float*)d_in[10];
    float* out = (float*)d_out;

    const int lstm_smem = 65536 + 8192 + 1024;   // 74752 B
    cudaFuncSetAttribute(k_lstm, cudaFuncAttributeMaxDynamicSharedMemorySize, lstm_smem);

    k_xz<<<BB * T_OUT / 8, 128>>>(inputs, Wk, bias);
    k_keys<<<BB * T_IN / 8, 128>>>(attended, W1, b1);
    k_lstm<<<BB, 512, lstm_smem>>>(Wr, out);
    k_attn<<<BB * (T_OUT / 2), 256>>>(attended, W2, b2, W3, b3, out);
}